// round 6
// baseline (speedup 1.0000x reference)
#include <cuda_runtime.h>
#include <math_constants.h>
#include <cstdint>

#define BATCH 4
#define SEQ   2048
#define DM    1024
#define NH    16
#define HD    64
#define MTOT  (BATCH*SEQ)   // 8192

// Scratch (device globals). All tf32 bit patterns.
__device__ uint32_t g_xt[MTOT*DM];
__device__ uint32_t g_Wt[4][DM*DM];
__device__ uint32_t g_Q[BATCH*NH*SEQ*HD]; // [b,h,s,hd] tf32, pre-scaled 0.125
__device__ uint32_t g_K[BATCH*NH*SEQ*HD];
__device__ uint32_t g_V[BATCH*NH*SEQ*HD];
__device__ uint32_t g_Y[MTOT*DM];         // [b,s,D] attn out, tf32

// ---------------------------------------------------------------------------
__device__ __forceinline__ uint32_t f2tf(float f) {
    uint32_t u;
    asm("cvt.rna.tf32.f32 %0, %1;" : "=r"(u) : "f"(f));
    return u;
}
__device__ __forceinline__ void mma8(float4& d, const uint32_t a[4], const uint32_t b[2]) {
    asm volatile(
        "mma.sync.aligned.m16n8k8.row.col.f32.tf32.tf32.f32 "
        "{%0,%1,%2,%3}, {%4,%5,%6,%7}, {%8,%9}, {%0,%1,%2,%3};"
        : "+f"(d.x), "+f"(d.y), "+f"(d.z), "+f"(d.w)
        : "r"(a[0]), "r"(a[1]), "r"(a[2]), "r"(a[3]), "r"(b[0]), "r"(b[1]));
}
__device__ __forceinline__ void cpa16(uint32_t dst, const void* src) {
    asm volatile("cp.async.cg.shared.global [%0], [%1], 16;" :: "r"(dst), "l"(src) : "memory");
}
__device__ __forceinline__ void cp_commit() {
    asm volatile("cp.async.commit_group;" ::: "memory");
}
template<int N>
__device__ __forceinline__ void cp_wait() {
    asm volatile("cp.async.wait_group %0;" :: "n"(N) : "memory");
}

__global__ void conv_tf32(const float4* __restrict__ in, uint4* __restrict__ out, int n4) {
    int i = blockIdx.x * blockDim.x + threadIdx.x;
    if (i < n4) {
        float4 v = in[i];
        out[i] = make_uint4(f2tf(v.x), f2tf(v.y), f2tf(v.z), f2tf(v.w));
    }
}

// ---------------------------------------------------------------------------
// GEMM + bias, tf32 in gmem. 128x128 tile, BK=32, 3-stage cp.async,
// ONE __syncthreads per iter, 2 CTAs/SM.
// MODE 0: tf32 bits head-split [b,h,s,hd] (scaled); MODE 1: fp32 [m,n].
// ---------------------------------------------------------------------------
#define AS_G   36                 // A row stride: (4g+t) banks, 144B = 16B-aligned
#define BS_G   136                // B row stride + row-parity XOR swizzle
#define A_STG  (128*AS_G)         // 4608 u32
#define B_STG  (32*BS_G)          // 4352 u32
#define G_SMEM (3*(A_STG + B_STG)*4)   // 107520 bytes

template<int MODE>
__global__ __launch_bounds__(256, 2)
void gemm_tc(const uint32_t* __restrict__ A,
             const uint32_t* __restrict__ W,
             const float* __restrict__ bias,
             void* __restrict__ Cout, float scale) {
    extern __shared__ uint32_t sm[];
    uint32_t* smA = sm;                    // 3 stages x [128][36]
    uint32_t* smB = sm + 3*A_STG;          // 3 stages x [32][136]
    const uint32_t smA_u = (uint32_t)__cvta_generic_to_shared(smA);
    const uint32_t smB_u = (uint32_t)__cvta_generic_to_shared(smB);

    const int tid  = threadIdx.x;
    const int lane = tid & 31;
    const int warp = tid >> 5;
    const int g = lane >> 2, t = lane & 3;
    const int wm = (warp >> 2) * 64;
    const int wn = (warp & 3)  * 32;
    const int bm = blockIdx.y * 128;
    const int bn = blockIdx.x * 128;

    // cp.async assignments (BK=32)
    const int a_m  = tid & 127;            // A row
    const int a_kh = (tid >> 7) * 16;      // k half: 0 or 16
    const int b_r  = tid >> 3;             // B k row 0..31
    const int b_c0 = (tid & 7) * 16;       // B col base
    const int b_sw = (b_r & 1) << 2;

    const uint32_t* Abase = A + (size_t)(bm + a_m) * DM + a_kh;
    const uint32_t* Wbase = W + (size_t)b_r * DM + bn + b_c0;

    #define G_ISSUE(kt) {                                                     \
        uint32_t da = smA_u + (((kt)%3)*A_STG + a_m*AS_G + a_kh)*4;           \
        const uint32_t* sa_ = Abase + (kt)*32;                                \
        cpa16(da,      sa_);     cpa16(da + 16, sa_ + 4);                     \
        cpa16(da + 32, sa_ + 8); cpa16(da + 48, sa_ + 12);                    \
        uint32_t db = smB_u + (((kt)%3)*B_STG + b_r*BS_G)*4;                  \
        const uint32_t* sb_ = Wbase + (size_t)(kt)*32*DM;                     \
        cpa16(db + (uint32_t)((b_c0)    ^ b_sw)*4, sb_);                      \
        cpa16(db + (uint32_t)((b_c0+4)  ^ b_sw)*4, sb_ + 4);                  \
        cpa16(db + (uint32_t)((b_c0+8)  ^ b_sw)*4, sb_ + 8);                  \
        cpa16(db + (uint32_t)((b_c0+12) ^ b_sw)*4, sb_ + 12);                 \
        cp_commit(); }

    float4 acc[4][4];
    #pragma unroll
    for (int i = 0; i < 4; i++)
        #pragma unroll
        for (int j = 0; j < 4; j++) acc[i][j] = make_float4(0.f,0.f,0.f,0.f);

    const int NITER = DM / 32;   // 32
    G_ISSUE(0); G_ISSUE(1);

    for (int kt = 0; kt < NITER; kt++) {
        if (kt < NITER-2) cp_wait<1>(); else cp_wait<0>();
        __syncthreads();
        if (kt + 2 < NITER) { G_ISSUE(kt+2); }

        const uint32_t* As = smA + (kt%3)*A_STG;
        const uint32_t* Bs = smB + (kt%3)*B_STG;
        #pragma unroll
        for (int ks = 0; ks < 4; ks++) {
            const int kk = ks*8 + t;
            const int sw = (t & 1) << 2;
            uint32_t bf[4][2];
            #pragma unroll
            for (int nt = 0; nt < 4; nt++) {
                int col = (wn + nt*8 + g) ^ sw;
                bf[nt][0] = Bs[kk*BS_G + col];
                bf[nt][1] = Bs[(kk+4)*BS_G + col];
            }
            #pragma unroll
            for (int mt = 0; mt < 4; mt++) {
                uint32_t af[4];
                int base = (wm + mt*16 + g)*AS_G + kk;
                af[0] = As[base];
                af[1] = As[base + 8*AS_G];
                af[2] = As[base + 4];
                af[3] = As[base + 8*AS_G + 4];
                #pragma unroll
                for (int nt = 0; nt < 4; nt++) mma8(acc[mt][nt], af, bf[nt]);
            }
        }
    }
    #undef G_ISSUE

    // epilogue
    #pragma unroll
    for (int mt = 0; mt < 4; mt++) {
        int m0 = bm + wm + mt*16 + g;
        #pragma unroll
        for (int nt = 0; nt < 4; nt++) {
            int n = bn + wn + nt*8 + 2*t;
            float2 bb = *(const float2*)(bias + n);
            float r0x = acc[mt][nt].x + bb.x, r0y = acc[mt][nt].y + bb.y;
            float r1x = acc[mt][nt].z + bb.x, r1y = acc[mt][nt].w + bb.y;
            if (MODE == 0) {
                uint32_t* C = (uint32_t*)Cout;
                int h = n >> 6, dd = n & 63;
                int b0i = m0 >> 11, s0 = m0 & (SEQ-1);
                *(uint2*)&C[(((size_t)(b0i*NH + h))*SEQ + s0)*HD + dd] =
                    make_uint2(f2tf(r0x*scale), f2tf(r0y*scale));
                int m1 = m0 + 8;
                int b1i = m1 >> 11, s1 = m1 & (SEQ-1);
                *(uint2*)&C[(((size_t)(b1i*NH + h))*SEQ + s1)*HD + dd] =
                    make_uint2(f2tf(r1x*scale), f2tf(r1y*scale));
            } else {
                float* C = (float*)Cout;
                *(float2*)&C[(size_t)m0*DM + n]     = make_float2(r0x, r0y);
                *(float2*)&C[(size_t)(m0+8)*DM + n] = make_float2(r1x, r1y);
            }
        }
    }
}

// ---------------------------------------------------------------------------
// Flash attention, tf32 mma. 128 q-rows/CTA, 8 warps x 16 q-rows.
// Q fragments loaded once from gmem into registers (no Q smem).
// P [128][68]; K/V 2-slot cp.async. smem 108.5KB -> 2 CTAs/SM.
// ---------------------------------------------------------------------------
#define PQS   68
#define KVS   72
#define KVSZ  (64*KVS)
#define PW    (128*PQS)
#define ATT_SMEM ((PW + 4*KVSZ) * 4)   // 108544 bytes

__global__ __launch_bounds__(256, 2)
void attn_tc(const uint32_t* __restrict__ Q, const uint32_t* __restrict__ K,
             const uint32_t* __restrict__ V, uint32_t* __restrict__ Y) {
    extern __shared__ uint32_t sm[];
    uint32_t* Ps = sm;                 // [128][68]
    uint32_t* Ks = sm + PW;            // 2 x [64][72], XOR swizzled
    uint32_t* Vs = Ks + 2*KVSZ;        // 2 x [64][72]
    const uint32_t smK_u = (uint32_t)__cvta_generic_to_shared(Ks);
    const uint32_t smV_u = (uint32_t)__cvta_generic_to_shared(Vs);

    const int tid  = threadIdx.x;
    const int lane = tid & 31;
    const int warp = tid >> 5;
    const int g = lane >> 2, t = lane & 3;
    const int wq = warp * 16;
    const int qb = blockIdx.x * 128;
    const int bh = blockIdx.y;

    const uint32_t* Kp = K + (size_t)bh * SEQ * HD;
    const uint32_t* Vp = V + (size_t)bh * SEQ * HD;

    #define AKV_ISSUE(kbi, slot) {                                            \
        const uint32_t* kp = Kp + (size_t)(kbi)*64*HD;                        \
        const uint32_t* vp = Vp + (size_t)(kbi)*64*HD;                        \
        uint32_t kb_ = smK_u + (slot)*KVSZ*4;                                 \
        uint32_t vb_ = smV_u + (slot)*KVSZ*4;                                 \
        _Pragma("unroll")                                                     \
        for (int it = 0; it < 4; it++) {                                      \
            int fl = it*256 + tid;                                            \
            int r = fl >> 4, c = (fl & 15) * 4;                               \
            int kc = c ^ ((r & 7) << 2);                                      \
            cpa16(kb_ + (uint32_t)(r*KVS + kc)*4, kp + (size_t)r*HD + c);     \
            cpa16(vb_ + (uint32_t)(r*KVS + c)*4,  vp + (size_t)r*HD + c);     \
        } }

    AKV_ISSUE(0, 0); cp_commit();
    AKV_ISSUE(1, 1); cp_commit();

    // Q fragments straight from gmem (tf32, pre-scaled); live for whole loop
    uint32_t qf[8][4];
    {
        const uint32_t* Qr0 = Q + ((size_t)bh * SEQ + qb + wq + g) * HD;
        const uint32_t* Qr1 = Qr0 + (size_t)8 * HD;
        #pragma unroll
        for (int ks = 0; ks < 8; ks++) {
            qf[ks][0] = Qr0[ks*8 + t];
            qf[ks][1] = Qr1[ks*8 + t];
            qf[ks][2] = Qr0[ks*8 + t + 4];
            qf[ks][3] = Qr1[ks*8 + t + 4];
        }
    }

    float4 of[8];
    #pragma unroll
    for (int nt = 0; nt < 8; nt++) of[nt] = make_float4(0.f,0.f,0.f,0.f);
    float m0 = -CUDART_INF_F, m1 = -CUDART_INF_F, l0 = 0.f, l1 = 0.f;

    cp_wait<1>();
    __syncthreads();

    const int NT = SEQ / 64;   // 32
    for (int kbi = 0; kbi < NT; kbi++) {
        const int cur = kbi & 1;
        const uint32_t* Kst = Ks + cur*KVSZ;
        const uint32_t* Vst = Vs + cur*KVSZ;

        // ---- S = Qscaled @ K^T (16 x 64 per warp) ----
        float4 sa[8];
        #pragma unroll
        for (int nt = 0; nt < 8; nt++) sa[nt] = make_float4(0.f,0.f,0.f,0.f);
        #pragma unroll
        for (int ks = 0; ks < 8; ks++) {
            #pragma unroll
            for (int nt = 0; nt < 8; nt++) {
                uint32_t kf[2];
                int rowb = (nt*8 + g)*KVS;
                int sw = g << 2;
                kf[0] = Kst[rowb + ((ks*8 + t) ^ sw)];
                kf[1] = Kst[rowb + ((ks*8 + t + 4) ^ sw)];
                mma8(sa[nt], qf[ks], kf);
            }
        }

        // ---- online softmax + P store ----
        {
            float mx0 = -CUDART_INF_F, mx1 = -CUDART_INF_F;
            #pragma unroll
            for (int nt = 0; nt < 8; nt++) {
                mx0 = fmaxf(mx0, fmaxf(sa[nt].x, sa[nt].y));
                mx1 = fmaxf(mx1, fmaxf(sa[nt].z, sa[nt].w));
            }
            mx0 = fmaxf(mx0, __shfl_xor_sync(0xffffffffu, mx0, 1));
            mx0 = fmaxf(mx0, __shfl_xor_sync(0xffffffffu, mx0, 2));
            mx1 = fmaxf(mx1, __shfl_xor_sync(0xffffffffu, mx1, 1));
            mx1 = fmaxf(mx1, __shfl_xor_sync(0xffffffffu, mx1, 2));
            float nm0 = fmaxf(m0, mx0), nm1 = fmaxf(m1, mx1);
            float al0 = __expf(m0 - nm0), al1 = __expf(m1 - nm1);
            float rs0 = 0.f, rs1 = 0.f;
            int r0 = (wq + g)*PQS;
            int r1 = r0 + 8*PQS;
            #pragma unroll
            for (int nt = 0; nt < 8; nt++) {
                float p00 = __expf(sa[nt].x - nm0);
                float p01 = __expf(sa[nt].y - nm0);
                float p10 = __expf(sa[nt].z - nm1);
                float p11 = __expf(sa[nt].w - nm1);
                rs0 += p00 + p01;
                rs1 += p10 + p11;
                int c = nt*8 + 2*t;
                *(uint2*)&Ps[r0 + c] = make_uint2(f2tf(p00), f2tf(p01));
                *(uint2*)&Ps[r1 + c] = make_uint2(f2tf(p10), f2tf(p11));
            }
            rs0 += __shfl_xor_sync(0xffffffffu, rs0, 1);
            rs0 += __shfl_xor_sync(0xffffffffu, rs0, 2);
            rs1 += __shfl_xor_sync(0xffffffffu, rs1, 1);
            rs1 += __shfl_xor_sync(0xffffffffu, rs1, 2);
            l0 = l0*al0 + rs0; m0 = nm0;
            l1 = l1*al1 + rs1; m1 = nm1;
            #pragma unroll
            for (int nt = 0; nt < 8; nt++) {
                of[nt].x *= al0; of[nt].y *= al0;
                of[nt].z *= al1; of[nt].w *= al1;
            }
        }
        __syncwarp();   // P visible to own warp's frag loads

        // ---- O += P @ V ----
        #pragma unroll
        for (int ks = 0; ks < 8; ks++) {
            uint32_t pf[4];
            int base = (wq + g)*PQS + ks*8 + t;
            pf[0] = Ps[base];
            pf[1] = Ps[base + 8*PQS];
            pf[2] = Ps[base + 4];
            pf[3] = Ps[base + 8*PQS + 4];
            #pragma unroll
            for (int nt = 0; nt < 8; nt++) {
                uint32_t vf[2];
                int a = (ks*8 + t)*KVS + nt*8 + g;
                vf[0] = Vst[a];
                vf[1] = Vst[a + 4*KVS];
                mma8(of[nt], pf, vf);
            }
        }

        __syncthreads();                 // all warps done reading slot cur
        if (kbi + 2 < NT) {
            AKV_ISSUE(kbi+2, cur); cp_commit();
            cp_wait<1>();                // tile kbi+1 complete
        } else {
            cp_wait<0>();
        }
        __syncthreads();                 // next slot visible to all threads
    }
    #undef AKV_ISSUE

    // epilogue: normalize, tf32, write Y [b,s,D]
    int b = bh >> 4, h = bh & (NH-1);
    float inv0 = 1.f / l0, inv1 = 1.f / l1;
    size_t row0 = (size_t)b * SEQ + qb + wq + g;
    #pragma unroll
    for (int nt = 0; nt < 8; nt++) {
        int dd = h*64 + nt*8 + 2*t;
        *(uint2*)&Y[row0*DM + dd] =
            make_uint2(f2tf(of[nt].x*inv0), f2tf(of[nt].y*inv0));
        *(uint2*)&Y[(row0 + 8)*DM + dd] =
            make_uint2(f2tf(of[nt].z*inv1), f2tf(of[nt].w*inv1));
    }
}

// ---------------------------------------------------------------------------
extern "C" void kernel_launch(void* const* d_in, const int* in_sizes, int n_in,
                              void* d_out, int out_size) {
    const float* x  = (const float*)d_in[0];
    const float* Wq = (const float*)d_in[1];
    const float* bq = (const float*)d_in[2];
    const float* Wk = (const float*)d_in[3];
    const float* bk = (const float*)d_in[4];
    const float* Wv = (const float*)d_in[5];
    const float* bv = (const float*)d_in[6];
    const float* Wo = (const float*)d_in[7];
    const float* bo = (const float*)d_in[8];
    float* out = (float*)d_out;

    uint32_t *xt, *wt, *qp, *kp, *vp, *yp;
    cudaGetSymbolAddress((void**)&xt, g_xt);
    cudaGetSymbolAddress((void**)&wt, g_Wt);
    cudaGetSymbolAddress((void**)&qp, g_Q);
    cudaGetSymbolAddress((void**)&kp, g_K);
    cudaGetSymbolAddress((void**)&vp, g_V);
    cudaGetSymbolAddress((void**)&yp, g_Y);
    uint32_t* wqt = wt;
    uint32_t* wkt = wt + (size_t)DM*DM;
    uint32_t* wvt = wt + (size_t)2*DM*DM;
    uint32_t* wot = wt + (size_t)3*DM*DM;

    int nx4 = MTOT*DM/4, nw4 = DM*DM/4;
    conv_tf32<<<nx4/256, 256>>>((const float4*)x,  (uint4*)xt,  nx4);
    conv_tf32<<<nw4/256, 256>>>((const float4*)Wq, (uint4*)wqt, nw4);
    conv_tf32<<<nw4/256, 256>>>((const float4*)Wk, (uint4*)wkt, nw4);
    conv_tf32<<<nw4/256, 256>>>((const float4*)Wv, (uint4*)wvt, nw4);
    conv_tf32<<<nw4/256, 256>>>((const float4*)Wo, (uint4*)wot, nw4);

    cudaFuncSetAttribute(gemm_tc<0>, cudaFuncAttributeMaxDynamicSharedMemorySize, G_SMEM);
    cudaFuncSetAttribute(gemm_tc<1>, cudaFuncAttributeMaxDynamicSharedMemorySize, G_SMEM);
    cudaFuncSetAttribute(attn_tc,    cudaFuncAttributeMaxDynamicSharedMemorySize, ATT_SMEM);

    dim3 gg(DM/128, MTOT/128);   // (8, 64)
    gemm_tc<0><<<gg, 256, G_SMEM>>>(xt, wqt, bq, qp, 0.125f);  // Q pre-scaled
    gemm_tc<0><<<gg, 256, G_SMEM>>>(xt, wkt, bk, kp, 1.0f);
    gemm_tc<0><<<gg, 256, G_SMEM>>>(xt, wvt, bv, vp, 1.0f);

    attn_tc<<<dim3(SEQ/128, BATCH*NH), 256, ATT_SMEM>>>(qp, kp, vp, yp);

    gemm_tc<1><<<gg, 256, G_SMEM>>>(yp, wot, bo, out, 1.0f);
}

// round 8
// speedup vs baseline: 1.5656x; 1.5656x over previous
#include <cuda_runtime.h>
#include <cuda_fp16.h>
#include <math_constants.h>
#include <cstdint>

#define BATCH 4
#define SEQ   2048
#define DM    1024
#define NH    16
#define HD    64
#define MTOT  (BATCH*SEQ)   // 8192

// Scratch (device globals). fp16 operands, fp32 accumulation in kernels.
__device__ __half g_xh[MTOT*DM];          // x as fp16 [m][k]
__device__ __half g_Wh[4][DM*DM];         // weights transposed [n][k] fp16
__device__ __half g_Q[BATCH*NH*SEQ*HD];   // [b,h,s,hd], pre-scaled 0.125
__device__ __half g_K[BATCH*NH*SEQ*HD];   // [b,h,s,hd]
__device__ __half g_V[BATCH*NH*SEQ*HD];   // TRANSPOSED: [b,h,hd,s]
__device__ __half g_Y[MTOT*DM];           // attn out [b,s,D] fp16

// ---------------------------------------------------------------------------
// helpers
// ---------------------------------------------------------------------------
__device__ __forceinline__ void mma16(float4& d, const uint32_t a[4], const uint32_t b[2]) {
    asm volatile(
        "mma.sync.aligned.m16n8k16.row.col.f32.f16.f16.f32 "
        "{%0,%1,%2,%3}, {%4,%5,%6,%7}, {%8,%9}, {%0,%1,%2,%3};"
        : "+f"(d.x), "+f"(d.y), "+f"(d.z), "+f"(d.w)
        : "r"(a[0]), "r"(a[1]), "r"(a[2]), "r"(a[3]), "r"(b[0]), "r"(b[1]));
}
__device__ __forceinline__ void cpa16(uint32_t dst, const void* src) {
    asm volatile("cp.async.cg.shared.global [%0], [%1], 16;" :: "r"(dst), "l"(src) : "memory");
}
__device__ __forceinline__ void cp_commit() {
    asm volatile("cp.async.commit_group;" ::: "memory");
}
template<int N>
__device__ __forceinline__ void cp_wait() {
    asm volatile("cp.async.wait_group %0;" :: "n"(N) : "memory");
}
__device__ __forceinline__ uint32_t h2u(__half2 h) { return *(uint32_t*)&h; }

// ---------------------------------------------------------------------------
// fp16 conversion kernels
// ---------------------------------------------------------------------------
__global__ void conv_f16(const float4* __restrict__ in, uint2* __restrict__ out, int n4) {
    int i = blockIdx.x * blockDim.x + threadIdx.x;
    if (i < n4) {
        float4 v = in[i];
        out[i] = make_uint2(h2u(__floats2half2_rn(v.x, v.y)),
                            h2u(__floats2half2_rn(v.z, v.w)));
    }
}
// out[n*DM + k] = fp16(in[k*DM + n])
__global__ void tr_f16(const float* __restrict__ in, __half* __restrict__ out) {
    __shared__ float t[32][33];
    int nb = blockIdx.x * 32, kb = blockIdx.y * 32;
    int tx = threadIdx.x, ty = threadIdx.y;
    #pragma unroll
    for (int j = 0; j < 4; j++)
        t[ty + 8*j][tx] = in[(size_t)(kb + ty + 8*j) * DM + nb + tx];
    __syncthreads();
    #pragma unroll
    for (int j = 0; j < 4; j++)
        out[(size_t)(nb + ty + 8*j) * DM + kb + tx] = __float2half_rn(t[tx][ty + 8*j]);
}

// ---------------------------------------------------------------------------
// GEMM + bias, fp16 mma m16n8k16: C = A[M,1024] @ Wt^T + bias (Wt=[N,K] fp16)
// 128x128 tile, BK=32, 3-stage cp.async, one barrier/iter, 2 CTAs/SM.
// MODE 0: fp16 head-split [b,h,s,hd] (scaled)
// MODE 1: fp32 row-major [m][n]
// MODE 2: fp16 transposed head-split [b,h,hd,s]  (for V)
// ---------------------------------------------------------------------------
#define AS_H   20                 // row stride in u32 (BK=32 fp16 = 16 u32 + pad)
#define STG_H  (128*AS_H)         // 2560 u32 per tile per stage
#define G_SMEM (3*2*STG_H*4)      // 61440 bytes

template<int MODE>
__global__ __launch_bounds__(256, 2)
void gemm_h(const __half* __restrict__ A,
            const __half* __restrict__ Wt,
            const float* __restrict__ bias,
            void* __restrict__ Cout, float scale) {
    extern __shared__ uint32_t sm[];
    uint32_t* smA = sm;                    // 3 x [128][20]
    uint32_t* smB = sm + 3*STG_H;          // 3 x [128][20]
    const uint32_t smA_u = (uint32_t)__cvta_generic_to_shared(smA);
    const uint32_t smB_u = (uint32_t)__cvta_generic_to_shared(smB);

    const int tid  = threadIdx.x;
    const int lane = tid & 31;
    const int warp = tid >> 5;
    const int g = lane >> 2, t = lane & 3;
    const int wm = (warp >> 2) * 64;
    const int wn = (warp & 3)  * 32;
    const int bm = blockIdx.y * 128;
    const int bn = blockIdx.x * 128;

    const __half* Ag = A  + (size_t)bm * DM;
    const __half* Bg = Wt + (size_t)bn * DM;

    // cp.async: per it, fl = it*256+tid; r = fl&127 (row), c = fl>>7 (16B chunk)
    #define G_ISSUE(kt) {                                                      \
        _Pragma("unroll")                                                      \
        for (int it = 0; it < 2; it++) {                                       \
            int fl = it*256 + tid;                                             \
            int r = fl & 127, c = fl >> 7;                                     \
            uint32_t off = (((kt)%3)*STG_H + r*AS_H + c*4) * 4;                \
            cpa16(smA_u + off, Ag + (size_t)r*DM + (kt)*32 + c*8);             \
            cpa16(smB_u + off, Bg + (size_t)r*DM + (kt)*32 + c*8);             \
        }                                                                      \
        cp_commit(); }

    float4 acc[4][4];
    #pragma unroll
    for (int i = 0; i < 4; i++)
        #pragma unroll
        for (int j = 0; j < 4; j++) acc[i][j] = make_float4(0.f,0.f,0.f,0.f);

    const int NITER = DM / 32;   // 32
    G_ISSUE(0); G_ISSUE(1);

    for (int kt = 0; kt < NITER; kt++) {
        if (kt < NITER-2) cp_wait<1>(); else cp_wait<0>();
        __syncthreads();
        if (kt + 2 < NITER) { G_ISSUE(kt+2); }

        const uint32_t* As = smA + (kt%3)*STG_H;
        const uint32_t* Bs = smB + (kt%3)*STG_H;
        #pragma unroll
        for (int ks = 0; ks < 2; ks++) {
            const int kk = ks*8 + t;    // u32 word index within row
            uint32_t bf[4][2];
            #pragma unroll
            for (int nt = 0; nt < 4; nt++) {
                int row = (wn + nt*8 + g)*AS_H;
                bf[nt][0] = Bs[row + kk];
                bf[nt][1] = Bs[row + kk + 4];
            }
            #pragma unroll
            for (int mt = 0; mt < 4; mt++) {
                uint32_t af[4];
                int base = (wm + mt*16 + g)*AS_H + kk;
                af[0] = As[base];
                af[1] = As[base + 8*AS_H];
                af[2] = As[base + 4];
                af[3] = As[base + 8*AS_H + 4];
                #pragma unroll
                for (int nt = 0; nt < 4; nt++) mma16(acc[mt][nt], af, bf[nt]);
            }
        }
    }
    #undef G_ISSUE

    // epilogue
    #pragma unroll
    for (int mt = 0; mt < 4; mt++) {
        int m0 = bm + wm + mt*16 + g;
        #pragma unroll
        for (int nt = 0; nt < 4; nt++) {
            int n = bn + wn + nt*8 + 2*t;
            float2 bb = *(const float2*)(bias + n);
            float r0x = acc[mt][nt].x + bb.x, r0y = acc[mt][nt].y + bb.y;
            float r1x = acc[mt][nt].z + bb.x, r1y = acc[mt][nt].w + bb.y;
            if (MODE == 0) {
                __half* C = (__half*)Cout;
                int h = n >> 6, dd = n & 63;
                int b0i = m0 >> 11, s0 = m0 & (SEQ-1);
                *(uint32_t*)&C[(((size_t)(b0i*NH + h))*SEQ + s0)*HD + dd] =
                    h2u(__floats2half2_rn(r0x*scale, r0y*scale));
                int m1 = m0 + 8;
                int b1i = m1 >> 11, s1 = m1 & (SEQ-1);
                *(uint32_t*)&C[(((size_t)(b1i*NH + h))*SEQ + s1)*HD + dd] =
                    h2u(__floats2half2_rn(r1x*scale, r1y*scale));
            } else if (MODE == 2) {
                // V transposed: [b,h,hd,s]
                __half* C = (__half*)Cout;
                int h = n >> 6, dd = n & 63;
                int b0i = m0 >> 11, s0 = m0 & (SEQ-1);
                size_t rb = ((size_t)(b0i*NH + h))*HD;
                C[(rb + dd  )*SEQ + s0    ] = __float2half_rn(r0x);
                C[(rb + dd+1)*SEQ + s0    ] = __float2half_rn(r0y);
                C[(rb + dd  )*SEQ + s0 + 8] = __float2half_rn(r1x);
                C[(rb + dd+1)*SEQ + s0 + 8] = __float2half_rn(r1y);
            } else {
                float* C = (float*)Cout;
                *(float2*)&C[(size_t)m0*DM + n]     = make_float2(r0x, r0y);
                *(float2*)&C[(size_t)(m0+8)*DM + n] = make_float2(r1x, r1y);
            }
        }
    }
}

// ---------------------------------------------------------------------------
// Flash attention, fp16 mma m16n8k16. 128 q-rows/CTA, 8 warps x 16 q.
// Q frags from gmem regs; K [key][hd], V [hd][key] (pre-transposed in gmem),
// P [q][key]; all fp16 pairs packed in u32, row stride 36 u32. 2-slot cp.async.
// ---------------------------------------------------------------------------
#define RS    36                  // row stride (u32) for K/V/P tiles
#define KVSZ  (64*RS)             // one 64-row tile
#define PW    (128*RS)
#define ATT_SMEM ((PW + 4*KVSZ) * 4)   // 55296 bytes

__global__ __launch_bounds__(256, 2)
void attn_h(const __half* __restrict__ Q, const __half* __restrict__ K,
            const __half* __restrict__ V, __half* __restrict__ Y) {
    extern __shared__ uint32_t sm[];
    uint32_t* Ps = sm;                 // [128][36]
    uint32_t* Ks = sm + PW;            // 2 x [64 key][36]
    uint32_t* Vs = Ks + 2*KVSZ;        // 2 x [64 hd][36]
    const uint32_t smK_u = (uint32_t)__cvta_generic_to_shared(Ks);
    const uint32_t smV_u = (uint32_t)__cvta_generic_to_shared(Vs);

    const int tid  = threadIdx.x;
    const int lane = tid & 31;
    const int warp = tid >> 5;
    const int g = lane >> 2, t = lane & 3;
    const int wq = warp * 16;
    const int qb = blockIdx.x * 128;
    const int bh = blockIdx.y;

    const __half* Kp = K + (size_t)bh * SEQ * HD;     // [key][hd]
    const __half* Vp = V + (size_t)bh * HD * SEQ;     // [hd][s]

    // K tile: 64 key-rows x 128B; V tile: 64 hd-rows x 64 keys (128B)
    #define AKV_ISSUE(kbi, slot) {                                             \
        const __half* kp = Kp + (size_t)(kbi)*64*HD;                           \
        const __half* vp = Vp + (size_t)(kbi)*64;                              \
        uint32_t kb_ = smK_u + (slot)*KVSZ*4;                                  \
        uint32_t vb_ = smV_u + (slot)*KVSZ*4;                                  \
        _Pragma("unroll")                                                      \
        for (int it = 0; it < 2; it++) {                                       \
            int fl = it*256 + tid;                                             \
            int r = fl & 63, c = fl >> 6;                                      \
            uint32_t off = (uint32_t)(r*RS + c*4)*4;                           \
            cpa16(kb_ + off, kp + (size_t)r*HD + c*8);                         \
            cpa16(vb_ + off, vp + (size_t)r*SEQ + c*8);                        \
        }                                                                      \
        cp_commit(); }

    AKV_ISSUE(0, 0); cp_commit();   // keep group structure: 1 group per tile
    AKV_ISSUE(1, 1);

    // Q fragments from gmem, live whole loop: 4 k-chunks x 4 u32
    uint32_t qf[4][4];
    {
        const uint32_t* Qr0 = (const uint32_t*)(Q + ((size_t)bh*SEQ + qb + wq + g)*HD);
        const uint32_t* Qr1 = (const uint32_t*)(Q + ((size_t)bh*SEQ + qb + wq + g + 8)*HD);
        #pragma unroll
        for (int ks = 0; ks < 4; ks++) {
            qf[ks][0] = Qr0[ks*8 + t];
            qf[ks][1] = Qr1[ks*8 + t];
            qf[ks][2] = Qr0[ks*8 + t + 4];
            qf[ks][3] = Qr1[ks*8 + t + 4];
        }
    }

    float4 of[8];
    #pragma unroll
    for (int nt = 0; nt < 8; nt++) of[nt] = make_float4(0.f,0.f,0.f,0.f);
    float m0 = -CUDART_INF_F, m1 = -CUDART_INF_F, l0 = 0.f, l1 = 0.f;

    cp_wait<1>();
    __syncthreads();

    const int NT = SEQ / 64;   // 32
    for (int kbi = 0; kbi < NT; kbi++) {
        const int cur = kbi & 1;
        const uint32_t* Kst = Ks + cur*KVSZ;
        const uint32_t* Vst = Vs + cur*KVSZ;

        // ---- S = Qscaled @ K^T (16 x 64 per warp) ----
        float4 sa[8];
        #pragma unroll
        for (int nt = 0; nt < 8; nt++) sa[nt] = make_float4(0.f,0.f,0.f,0.f);
        #pragma unroll
        for (int ks = 0; ks < 4; ks++) {
            #pragma unroll
            for (int nt = 0; nt < 8; nt++) {
                uint32_t kf[2];
                int rowb = (nt*8 + g)*RS + ks*8 + t;
                kf[0] = Kst[rowb];
                kf[1] = Kst[rowb + 4];
                mma16(sa[nt], qf[ks], kf);
            }
        }

        // ---- online softmax + P store (fp16 pairs) ----
        {
            float mx0 = -CUDART_INF_F, mx1 = -CUDART_INF_F;
            #pragma unroll
            for (int nt = 0; nt < 8; nt++) {
                mx0 = fmaxf(mx0, fmaxf(sa[nt].x, sa[nt].y));
                mx1 = fmaxf(mx1, fmaxf(sa[nt].z, sa[nt].w));
            }
            mx0 = fmaxf(mx0, __shfl_xor_sync(0xffffffffu, mx0, 1));
            mx0 = fmaxf(mx0, __shfl_xor_sync(0xffffffffu, mx0, 2));
            mx1 = fmaxf(mx1, __shfl_xor_sync(0xffffffffu, mx1, 1));
            mx1 = fmaxf(mx1, __shfl_xor_sync(0xffffffffu, mx1, 2));
            float nm0 = fmaxf(m0, mx0), nm1 = fmaxf(m1, mx1);
            float al0 = __expf(m0 - nm0), al1 = __expf(m1 - nm1);
            float rs0 = 0.f, rs1 = 0.f;
            int r0 = (wq + g)*RS;
            int r1 = r0 + 8*RS;
            #pragma unroll
            for (int nt = 0; nt < 8; nt++) {
                float p00 = __expf(sa[nt].x - nm0);
                float p01 = __expf(sa[nt].y - nm0);
                float p10 = __expf(sa[nt].z - nm1);
                float p11 = __expf(sa[nt].w - nm1);
                rs0 += p00 + p01;
                rs1 += p10 + p11;
                int w = nt*4 + t;   // u32 word covering keys nt*8+2t, +1
                Ps[r0 + w] = h2u(__floats2half2_rn(p00, p01));
                Ps[r1 + w] = h2u(__floats2half2_rn(p10, p11));
            }
            rs0 += __shfl_xor_sync(0xffffffffu, rs0, 1);
            rs0 += __shfl_xor_sync(0xffffffffu, rs0, 2);
            rs1 += __shfl_xor_sync(0xffffffffu, rs1, 1);
            rs1 += __shfl_xor_sync(0xffffffffu, rs1, 2);
            l0 = l0*al0 + rs0; m0 = nm0;
            l1 = l1*al1 + rs1; m1 = nm1;
            #pragma unroll
            for (int nt = 0; nt < 8; nt++) {
                of[nt].x *= al0; of[nt].y *= al0;
                of[nt].z *= al1; of[nt].w *= al1;
            }
        }
        __syncwarp();   // P visible to own warp's frag loads

        // ---- O += P @ V  (A=P [q][key], B=V^T [hd][key]) ----
        #pragma unroll
        for (int ks = 0; ks < 4; ks++) {
            uint32_t pf[4];
            int base = (wq + g)*RS + ks*8 + t;
            pf[0] = Ps[base];
            pf[1] = Ps[base + 8*RS];
            pf[2] = Ps[base + 4];
            pf[3] = Ps[base + 8*RS + 4];
            #pragma unroll
            for (int nt = 0; nt < 8; nt++) {
                uint32_t vf[2];
                int a = (nt*8 + g)*RS + ks*8 + t;
                vf[0] = Vst[a];
                vf[1] = Vst[a + 4];
                mma16(of[nt], pf, vf);
            }
        }

        __syncthreads();                 // all warps done with slot cur
        if (kbi + 2 < NT) {
            AKV_ISSUE(kbi+2, cur);
            cp_wait<1>();                // tile kbi+1 landed
        } else {
            cp_wait<0>();
        }
        __syncthreads();
    }
    #undef AKV_ISSUE

    // epilogue: normalize, fp16, write Y [b,s,D]
    int b = bh >> 4, h = bh & (NH-1);
    float inv0 = 1.f / l0, inv1 = 1.f / l1;
    size_t row0 = (size_t)b * SEQ + qb + wq + g;
    #pragma unroll
    for (int nt = 0; nt < 8; nt++) {
        int dd = h*64 + nt*8 + 2*t;
        *(uint32_t*)&Y[row0*DM + dd] =
            h2u(__floats2half2_rn(of[nt].x*inv0, of[nt].y*inv0));
        *(uint32_t*)&Y[(row0 + 8)*DM + dd] =
            h2u(__floats2half2_rn(of[nt].z*inv1, of[nt].w*inv1));
    }
}

// ---------------------------------------------------------------------------
extern "C" void kernel_launch(void* const* d_in, const int* in_sizes, int n_in,
                              void* d_out, int out_size) {
    const float* x  = (const float*)d_in[0];
    const float* Wq = (const float*)d_in[1];
    const float* bq = (const float*)d_in[2];
    const float* Wk = (const float*)d_in[3];
    const float* bk = (const float*)d_in[4];
    const float* Wv = (const float*)d_in[5];
    const float* bv = (const float*)d_in[6];
    const float* Wo = (const float*)d_in[7];
    const float* bo = (const float*)d_in[8];
    float* out = (float*)d_out;

    __half *xh, *wh, *qp, *kp, *vp, *yp;
    cudaGetSymbolAddress((void**)&xh, g_xh);
    cudaGetSymbolAddress((void**)&wh, g_Wh);
    cudaGetSymbolAddress((void**)&qp, g_Q);
    cudaGetSymbolAddress((void**)&kp, g_K);
    cudaGetSymbolAddress((void**)&vp, g_V);
    cudaGetSymbolAddress((void**)&yp, g_Y);
    __half* wqh = wh;
    __half* wkh = wh + (size_t)DM*DM;
    __half* wvh = wh + (size_t)2*DM*DM;
    __half* woh = wh + (size_t)3*DM*DM;

    // x -> fp16; weights -> transposed [n][k] fp16
    int nx4 = MTOT*DM/4;
    conv_f16<<<nx4/256, 256>>>((const float4*)x, (uint2*)xh, nx4);
    dim3 tg(DM/32, DM/32), tb(32, 8);
    tr_f16<<<tg, tb>>>(Wq, wqh);
    tr_f16<<<tg, tb>>>(Wk, wkh);
    tr_f16<<<tg, tb>>>(Wv, wvh);
    tr_f16<<<tg, tb>>>(Wo, woh);

    cudaFuncSetAttribute(gemm_h<0>, cudaFuncAttributeMaxDynamicSharedMemorySize, G_SMEM);
    cudaFuncSetAttribute(gemm_h<1>, cudaFuncAttributeMaxDynamicSharedMemorySize, G_SMEM);
    cudaFuncSetAttribute(gemm_h<2>, cudaFuncAttributeMaxDynamicSharedMemorySize, G_SMEM);
    cudaFuncSetAttribute(attn_h,    cudaFuncAttributeMaxDynamicSharedMemorySize, ATT_SMEM);

    dim3 gg(DM/128, MTOT/128);   // (8, 64)
    gemm_h<0><<<gg, 256, G_SMEM>>>(xh, wqh, bq, qp, 0.125f);  // Q pre-scaled
    gemm_h<0><<<gg, 256, G_SMEM>>>(xh, wkh, bk, kp, 1.0f);
    gemm_h<2><<<gg, 256, G_SMEM>>>(xh, wvh, bv, vp, 1.0f);    // V transposed

    attn_h<<<dim3(SEQ/128, BATCH*NH), 256, ATT_SMEM>>>(qp, kp, vp, yp);

    gemm_h<1><<<gg, 256, G_SMEM>>>(yp, woh, bo, out, 1.0f);
}

// round 9
// speedup vs baseline: 1.7776x; 1.1354x over previous
#include <cuda_runtime.h>
#include <cuda_fp16.h>
#include <math_constants.h>
#include <cstdint>

#define BATCH 4
#define SEQ   2048
#define DM    1024
#define NH    16
#define HD    64
#define MTOT  (BATCH*SEQ)   // 8192

// Scratch (device globals). fp16 operands, fp32 accumulation in kernels.
__device__ __half g_xh[MTOT*DM];          // x as fp16 [m][k]
__device__ __half g_Wh[4][DM*DM];         // weights transposed [n][k] fp16
__device__ __half g_Q[BATCH*NH*SEQ*HD];   // [b,h,s,hd], pre-scaled 0.125
__device__ __half g_K[BATCH*NH*SEQ*HD];   // [b,h,s,hd]
__device__ __half g_V[BATCH*NH*SEQ*HD];   // TRANSPOSED: [b,h,hd,s]
__device__ __half g_Y[MTOT*DM];           // attn out [b,s,D] fp16

// ---------------------------------------------------------------------------
// helpers
// ---------------------------------------------------------------------------
__device__ __forceinline__ void mma16(float4& d, const uint32_t a[4], const uint32_t b[2]) {
    asm volatile(
        "mma.sync.aligned.m16n8k16.row.col.f32.f16.f16.f32 "
        "{%0,%1,%2,%3}, {%4,%5,%6,%7}, {%8,%9}, {%0,%1,%2,%3};"
        : "+f"(d.x), "+f"(d.y), "+f"(d.z), "+f"(d.w)
        : "r"(a[0]), "r"(a[1]), "r"(a[2]), "r"(a[3]), "r"(b[0]), "r"(b[1]));
}
__device__ __forceinline__ void ldsm4(uint32_t* r, uint32_t addr) {
    asm volatile("ldmatrix.sync.aligned.m8n8.x4.shared.b16 {%0,%1,%2,%3}, [%4];"
        : "=r"(r[0]), "=r"(r[1]), "=r"(r[2]), "=r"(r[3]) : "r"(addr));
}
__device__ __forceinline__ void cpa16(uint32_t dst, const void* src) {
    asm volatile("cp.async.cg.shared.global [%0], [%1], 16;" :: "r"(dst), "l"(src) : "memory");
}
__device__ __forceinline__ void cp_commit() {
    asm volatile("cp.async.commit_group;" ::: "memory");
}
template<int N>
__device__ __forceinline__ void cp_wait() {
    asm volatile("cp.async.wait_group %0;" :: "n"(N) : "memory");
}
__device__ __forceinline__ uint32_t h2u(__half2 h) { return *(uint32_t*)&h; }

// ---------------------------------------------------------------------------
// fp16 conversion kernels
// ---------------------------------------------------------------------------
__global__ void conv_f16(const float4* __restrict__ in, uint2* __restrict__ out, int n4) {
    int i = blockIdx.x * blockDim.x + threadIdx.x;
    if (i < n4) {
        float4 v = in[i];
        out[i] = make_uint2(h2u(__floats2half2_rn(v.x, v.y)),
                            h2u(__floats2half2_rn(v.z, v.w)));
    }
}
// out[n*DM + k] = fp16(in[k*DM + n]); z selects one of 4 weights
__global__ void tr_f16(const float* const* __restrict__ ws, __half* __restrict__ out0) {
    __shared__ float t[32][33];
    const float* in = ws[blockIdx.z];
    __half* out = out0 + (size_t)blockIdx.z * DM * DM;
    int nb = blockIdx.x * 32, kb = blockIdx.y * 32;
    int tx = threadIdx.x, ty = threadIdx.y;
    #pragma unroll
    for (int j = 0; j < 4; j++)
        t[ty + 8*j][tx] = in[(size_t)(kb + ty + 8*j) * DM + nb + tx];
    __syncthreads();
    #pragma unroll
    for (int j = 0; j < 4; j++)
        out[(size_t)(nb + ty + 8*j) * DM + kb + tx] = __float2half_rn(t[tx][ty + 8*j]);
}
__device__ const float* g_wptrs[4];   // filled via cudaMemcpyToSymbol-free trick below
__global__ void set_wptrs(const float* a, const float* b, const float* c, const float* d) {
    g_wptrs[0] = a; g_wptrs[1] = b; g_wptrs[2] = c; g_wptrs[3] = d;
}

// ---------------------------------------------------------------------------
// Fused QKV GEMM + bias (z = 0:Q, 1:K, 2:V) and MODE-templated single GEMM.
// C = A[M,1024] @ Wt^T + bias (Wt=[N,K] fp16), 128x128 tile, BK=32,
// 3-stage cp.async, ldmatrix fragment loads, one barrier/iter, 2 CTAs/SM.
// ---------------------------------------------------------------------------
#define AS_H   20                 // row stride in u32
#define STG_H  (128*AS_H)         // 2560 u32 per operand per stage
#define G_SMEM (3*2*STG_H*4)      // 61440 bytes

struct GemmCore {
    float4 acc[4][4];
};

// out_mode: 0 = fp16 head-split (scaled), 1 = fp32 row-major, 2 = fp16 V-transposed
__device__ __forceinline__ void gemm_body(
    const __half* Ag, const __half* Bg, const float* bias,
    void* Cout, float scale, int out_mode,
    uint32_t* sm, int bm, int bn)
{
    uint32_t* smA = sm;
    uint32_t* smB = sm + 3*STG_H;
    const uint32_t smA_u = (uint32_t)__cvta_generic_to_shared(smA);
    const uint32_t smB_u = (uint32_t)__cvta_generic_to_shared(smB);

    const int tid  = threadIdx.x;
    const int lane = tid & 31;
    const int warp = tid >> 5;
    const int g = lane >> 2, t = lane & 3;
    const int wm = (warp >> 2) * 64;
    const int wn = (warp & 3)  * 32;

    // ldmatrix lane address components
    const int arow = (lane & 7) + ((lane >> 3) & 1) * 8;   // A-type
    const int achk = (lane >> 4) & 1;
    const int brow = (lane & 7) + ((lane >> 4) & 1) * 8;   // B-type
    const int bchk = (lane >> 3) & 1;

    #define G_ISSUE(kt) {                                                      \
        _Pragma("unroll")                                                      \
        for (int it = 0; it < 2; it++) {                                       \
            int fl = it*256 + tid;                                             \
            int r = fl & 127, c = fl >> 7;                                     \
            uint32_t off = (((kt)%3)*STG_H + r*AS_H + c*4) * 4;                \
            cpa16(smA_u + off, Ag + (size_t)r*DM + (kt)*32 + c*8);             \
            cpa16(smB_u + off, Bg + (size_t)r*DM + (kt)*32 + c*8);             \
        }                                                                      \
        cp_commit(); }

    float4 acc[4][4];
    #pragma unroll
    for (int i = 0; i < 4; i++)
        #pragma unroll
        for (int j = 0; j < 4; j++) acc[i][j] = make_float4(0.f,0.f,0.f,0.f);

    const int NITER = DM / 32;   // 32
    G_ISSUE(0); G_ISSUE(1);

    for (int kt = 0; kt < NITER; kt++) {
        if (kt < NITER-2) cp_wait<1>(); else cp_wait<0>();
        __syncthreads();
        if (kt + 2 < NITER) { G_ISSUE(kt+2); }

        const uint32_t sA = smA_u + (kt%3)*STG_H*4;
        const uint32_t sB = smB_u + (kt%3)*STG_H*4;
        #pragma unroll
        for (int ks = 0; ks < 2; ks++) {
            uint32_t af[4][4];
            #pragma unroll
            for (int mt = 0; mt < 4; mt++)
                ldsm4(af[mt], sA + (uint32_t)((wm + mt*16 + arow)*AS_H*4 + ks*32 + achk*16));
            #pragma unroll
            for (int n2 = 0; n2 < 2; n2++) {
                uint32_t bf[4];
                ldsm4(bf, sB + (uint32_t)((wn + n2*16 + brow)*AS_H*4 + ks*32 + bchk*16));
                #pragma unroll
                for (int mt = 0; mt < 4; mt++) {
                    mma16(acc[mt][2*n2],   af[mt], bf);
                    mma16(acc[mt][2*n2+1], af[mt], bf+2);
                }
            }
        }
    }
    #undef G_ISSUE

    // epilogue
    #pragma unroll
    for (int mt = 0; mt < 4; mt++) {
        int m0 = bm + wm + mt*16 + g;
        #pragma unroll
        for (int nt = 0; nt < 4; nt++) {
            int n = bn + wn + nt*8 + 2*t;
            float2 bb = *(const float2*)(bias + n);
            float r0x = acc[mt][nt].x + bb.x, r0y = acc[mt][nt].y + bb.y;
            float r1x = acc[mt][nt].z + bb.x, r1y = acc[mt][nt].w + bb.y;
            if (out_mode == 0) {
                __half* C = (__half*)Cout;
                int h = n >> 6, dd = n & 63;
                int b0i = m0 >> 11, s0 = m0 & (SEQ-1);
                *(uint32_t*)&C[(((size_t)(b0i*NH + h))*SEQ + s0)*HD + dd] =
                    h2u(__floats2half2_rn(r0x*scale, r0y*scale));
                int m1 = m0 + 8;
                int b1i = m1 >> 11, s1 = m1 & (SEQ-1);
                *(uint32_t*)&C[(((size_t)(b1i*NH + h))*SEQ + s1)*HD + dd] =
                    h2u(__floats2half2_rn(r1x*scale, r1y*scale));
            } else if (out_mode == 2) {
                __half* C = (__half*)Cout;
                int h = n >> 6, dd = n & 63;
                int b0i = m0 >> 11, s0 = m0 & (SEQ-1);
                size_t rb = ((size_t)(b0i*NH + h))*HD;
                C[(rb + dd  )*SEQ + s0    ] = __float2half_rn(r0x);
                C[(rb + dd+1)*SEQ + s0    ] = __float2half_rn(r0y);
                C[(rb + dd  )*SEQ + s0 + 8] = __float2half_rn(r1x);
                C[(rb + dd+1)*SEQ + s0 + 8] = __float2half_rn(r1y);
            } else {
                float* C = (float*)Cout;
                *(float2*)&C[(size_t)m0*DM + n]     = make_float2(r0x, r0y);
                *(float2*)&C[(size_t)(m0+8)*DM + n] = make_float2(r1x, r1y);
            }
        }
    }
}

__global__ __launch_bounds__(256, 2)
void gemm_qkv(const __half* __restrict__ A, const __half* __restrict__ Wh4,
              const float* __restrict__ bq, const float* __restrict__ bk,
              const float* __restrict__ bv,
              __half* __restrict__ Qo, __half* __restrict__ Ko, __half* __restrict__ Vo) {
    extern __shared__ uint32_t sm[];
    const int z = blockIdx.z;
    const __half* Wt  = Wh4 + (size_t)z * DM * DM;
    const float* bias = (z == 0) ? bq : (z == 1) ? bk : bv;
    void* out   = (z == 0) ? (void*)Qo : (z == 1) ? (void*)Ko : (void*)Vo;
    float scale = (z == 0) ? 0.125f : 1.0f;
    int   mode  = (z == 2) ? 2 : 0;
    gemm_body(A + (size_t)blockIdx.y*128*DM, Wt + (size_t)blockIdx.x*128*DM,
              bias, out, scale, mode, sm, blockIdx.y*128, blockIdx.x*128);
}

__global__ __launch_bounds__(256, 2)
void gemm_out(const __half* __restrict__ A, const __half* __restrict__ Wt,
              const float* __restrict__ bias, float* __restrict__ C) {
    extern __shared__ uint32_t sm[];
    gemm_body(A + (size_t)blockIdx.y*128*DM, Wt + (size_t)blockIdx.x*128*DM,
              bias, (void*)C, 1.0f, 1, sm, blockIdx.y*128, blockIdx.x*128);
}

// ---------------------------------------------------------------------------
// Flash attention, fp16 mma m16n8k16 + ldmatrix. 128 q-rows/CTA, 8 warps.
// K [key][hd], V [hd][key] (pre-transposed), P [q][key]; stride 36 u32.
// ---------------------------------------------------------------------------
#define RS    36
#define KVSZ  (64*RS)
#define PW    (128*RS)
#define ATT_SMEM ((PW + 4*KVSZ) * 4)   // 55296 bytes

__global__ __launch_bounds__(256, 2)
void attn_h(const __half* __restrict__ Q, const __half* __restrict__ K,
            const __half* __restrict__ V, __half* __restrict__ Y) {
    extern __shared__ uint32_t sm[];
    uint32_t* Ps = sm;                 // [128][36]
    uint32_t* Ks = sm + PW;            // 2 x [64 key][36]
    uint32_t* Vs = Ks + 2*KVSZ;        // 2 x [64 hd][36]
    const uint32_t smP_u = (uint32_t)__cvta_generic_to_shared(Ps);
    const uint32_t smK_u = (uint32_t)__cvta_generic_to_shared(Ks);
    const uint32_t smV_u = (uint32_t)__cvta_generic_to_shared(Vs);

    const int tid  = threadIdx.x;
    const int lane = tid & 31;
    const int warp = tid >> 5;
    const int g = lane >> 2, t = lane & 3;
    const int wq = warp * 16;
    const int qb = blockIdx.x * 128;
    const int bh = blockIdx.y;

    const int arow = (lane & 7) + ((lane >> 3) & 1) * 8;   // A-type (P)
    const int achk = (lane >> 4) & 1;
    const int brow = (lane & 7) + ((lane >> 4) & 1) * 8;   // B-type (K, V)
    const int bchk = (lane >> 3) & 1;

    const __half* Kp = K + (size_t)bh * SEQ * HD;     // [key][hd]
    const __half* Vp = V + (size_t)bh * HD * SEQ;     // [hd][s]

    #define AKV_ISSUE(kbi, slot) {                                             \
        const __half* kp = Kp + (size_t)(kbi)*64*HD;                           \
        const __half* vp = Vp + (size_t)(kbi)*64;                              \
        uint32_t kb_ = smK_u + (slot)*KVSZ*4;                                  \
        uint32_t vb_ = smV_u + (slot)*KVSZ*4;                                  \
        _Pragma("unroll")                                                      \
        for (int it = 0; it < 2; it++) {                                       \
            int fl = it*256 + tid;                                             \
            int r = fl & 63, c = fl >> 6;                                      \
            uint32_t off = (uint32_t)(r*RS + c*4)*4;                           \
            cpa16(kb_ + off, kp + (size_t)r*HD + c*8);                         \
            cpa16(vb_ + off, vp + (size_t)r*SEQ + c*8);                        \
        }                                                                      \
        cp_commit(); }

    AKV_ISSUE(0, 0);
    AKV_ISSUE(1, 1);

    // Q fragments from gmem, live whole loop
    uint32_t qf[4][4];
    {
        const uint32_t* Qr0 = (const uint32_t*)(Q + ((size_t)bh*SEQ + qb + wq + g)*HD);
        const uint32_t* Qr1 = (const uint32_t*)(Q + ((size_t)bh*SEQ + qb + wq + g + 8)*HD);
        #pragma unroll
        for (int ks = 0; ks < 4; ks++) {
            qf[ks][0] = Qr0[ks*8 + t];
            qf[ks][1] = Qr1[ks*8 + t];
            qf[ks][2] = Qr0[ks*8 + t + 4];
            qf[ks][3] = Qr1[ks*8 + t + 4];
        }
    }

    float4 of[8];
    #pragma unroll
    for (int nt = 0; nt < 8; nt++) of[nt] = make_float4(0.f,0.f,0.f,0.f);
    float m0 = -CUDART_INF_F, m1 = -CUDART_INF_F, l0 = 0.f, l1 = 0.f;

    cp_wait<1>();
    __syncthreads();

    const int NT = SEQ / 64;   // 32
    for (int kbi = 0; kbi < NT; kbi++) {
        const int cur = kbi & 1;
        const uint32_t Kst_u = smK_u + cur*KVSZ*4;
        const uint32_t Vst_u = smV_u + cur*KVSZ*4;

        // ---- S = Qscaled @ K^T ----
        float4 sa[8];
        #pragma unroll
        for (int nt = 0; nt < 8; nt++) sa[nt] = make_float4(0.f,0.f,0.f,0.f);
        #pragma unroll
        for (int ks = 0; ks < 4; ks++) {
            #pragma unroll
            for (int n2 = 0; n2 < 4; n2++) {
                uint32_t kf[4];
                ldsm4(kf, Kst_u + (uint32_t)((n2*16 + brow)*RS*4 + ks*32 + bchk*16));
                mma16(sa[2*n2],   qf[ks], kf);
                mma16(sa[2*n2+1], qf[ks], kf+2);
            }
        }

        // ---- online softmax + P store ----
        {
            float mx0 = -CUDART_INF_F, mx1 = -CUDART_INF_F;
            #pragma unroll
            for (int nt = 0; nt < 8; nt++) {
                mx0 = fmaxf(mx0, fmaxf(sa[nt].x, sa[nt].y));
                mx1 = fmaxf(mx1, fmaxf(sa[nt].z, sa[nt].w));
            }
            mx0 = fmaxf(mx0, __shfl_xor_sync(0xffffffffu, mx0, 1));
            mx0 = fmaxf(mx0, __shfl_xor_sync(0xffffffffu, mx0, 2));
            mx1 = fmaxf(mx1, __shfl_xor_sync(0xffffffffu, mx1, 1));
            mx1 = fmaxf(mx1, __shfl_xor_sync(0xffffffffu, mx1, 2));
            float nm0 = fmaxf(m0, mx0), nm1 = fmaxf(m1, mx1);
            float al0 = __expf(m0 - nm0), al1 = __expf(m1 - nm1);
            float rs0 = 0.f, rs1 = 0.f;
            int r0 = (wq + g)*RS;
            int r1 = r0 + 8*RS;
            #pragma unroll
            for (int nt = 0; nt < 8; nt++) {
                float p00 = __expf(sa[nt].x - nm0);
                float p01 = __expf(sa[nt].y - nm0);
                float p10 = __expf(sa[nt].z - nm1);
                float p11 = __expf(sa[nt].w - nm1);
                rs0 += p00 + p01;
                rs1 += p10 + p11;
                int w = nt*4 + t;
                Ps[r0 + w] = h2u(__floats2half2_rn(p00, p01));
                Ps[r1 + w] = h2u(__floats2half2_rn(p10, p11));
            }
            rs0 += __shfl_xor_sync(0xffffffffu, rs0, 1);
            rs0 += __shfl_xor_sync(0xffffffffu, rs0, 2);
            rs1 += __shfl_xor_sync(0xffffffffu, rs1, 1);
            rs1 += __shfl_xor_sync(0xffffffffu, rs1, 2);
            l0 = l0*al0 + rs0; m0 = nm0;
            l1 = l1*al1 + rs1; m1 = nm1;
            #pragma unroll
            for (int nt = 0; nt < 8; nt++) {
                of[nt].x *= al0; of[nt].y *= al0;
                of[nt].z *= al1; of[nt].w *= al1;
            }
        }
        __syncwarp();   // P stores -> own warp's ldmatrix

        // ---- O += P @ V ----
        #pragma unroll
        for (int ks = 0; ks < 4; ks++) {
            uint32_t pf[4];
            ldsm4(pf, smP_u + (uint32_t)((wq + arow)*RS*4 + ks*32 + achk*16));
            #pragma unroll
            for (int n2 = 0; n2 < 4; n2++) {
                uint32_t vf[4];
                ldsm4(vf, Vst_u + (uint32_t)((n2*16 + brow)*RS*4 + ks*32 + bchk*16));
                mma16(of[2*n2],   pf, vf);
                mma16(of[2*n2+1], pf, vf+2);
            }
        }

        __syncthreads();
        if (kbi + 2 < NT) {
            AKV_ISSUE(kbi+2, cur);
            cp_wait<1>();
        } else {
            cp_wait<0>();
        }
        __syncthreads();
    }
    #undef AKV_ISSUE

    // epilogue
    int b = bh >> 4, h = bh & (NH-1);
    float inv0 = 1.f / l0, inv1 = 1.f / l1;
    size_t row0 = (size_t)b * SEQ + qb + wq + g;
    #pragma unroll
    for (int nt = 0; nt < 8; nt++) {
        int dd = h*64 + nt*8 + 2*t;
        *(uint32_t*)&Y[row0*DM + dd] =
            h2u(__floats2half2_rn(of[nt].x*inv0, of[nt].y*inv0));
        *(uint32_t*)&Y[(row0 + 8)*DM + dd] =
            h2u(__floats2half2_rn(of[nt].z*inv1, of[nt].w*inv1));
    }
}

// ---------------------------------------------------------------------------
extern "C" void kernel_launch(void* const* d_in, const int* in_sizes, int n_in,
                              void* d_out, int out_size) {
    const float* x  = (const float*)d_in[0];
    const float* Wq = (const float*)d_in[1];
    const float* bq = (const float*)d_in[2];
    const float* Wk = (const float*)d_in[3];
    const float* bk = (const float*)d_in[4];
    const float* Wv = (const float*)d_in[5];
    const float* bv = (const float*)d_in[6];
    const float* Wo = (const float*)d_in[7];
    const float* bo = (const float*)d_in[8];
    float* out = (float*)d_out;

    __half *xh, *wh, *qp, *kp, *vp, *yp;
    cudaGetSymbolAddress((void**)&xh, g_xh);
    cudaGetSymbolAddress((void**)&wh, g_Wh);
    cudaGetSymbolAddress((void**)&qp, g_Q);
    cudaGetSymbolAddress((void**)&kp, g_K);
    cudaGetSymbolAddress((void**)&vp, g_V);
    cudaGetSymbolAddress((void**)&yp, g_Y);
    const float** wptrs;
    cudaGetSymbolAddress((void**)&wptrs, g_wptrs);

    // x -> fp16; weights -> transposed [n][k] fp16 (z-batched)
    int nx4 = MTOT*DM/4;
    conv_f16<<<nx4/256, 256>>>((const float4*)x, (uint2*)xh, nx4);
    set_wptrs<<<1, 1>>>(Wq, Wk, Wv, Wo);
    dim3 tg(DM/32, DM/32, 4), tb(32, 8);
    tr_f16<<<tg, tb>>>(wptrs, wh);

    cudaFuncSetAttribute(gemm_qkv, cudaFuncAttributeMaxDynamicSharedMemorySize, G_SMEM);
    cudaFuncSetAttribute(gemm_out, cudaFuncAttributeMaxDynamicSharedMemorySize, G_SMEM);
    cudaFuncSetAttribute(attn_h,   cudaFuncAttributeMaxDynamicSharedMemorySize, ATT_SMEM);

    // fused Q/K/V projections
    gemm_qkv<<<dim3(DM/128, MTOT/128, 3), 256, G_SMEM>>>(
        xh, wh, bq, bk, bv, qp, kp, vp);

    attn_h<<<dim3(SEQ/128, BATCH*NH), 256, ATT_SMEM>>>(qp, kp, vp, yp);

    gemm_out<<<dim3(DM/128, MTOT/128), 256, G_SMEM>>>(
        yp, wh + (size_t)3*DM*DM, bo, out);
}